// round 1
// baseline (speedup 1.0000x reference)
#include <cuda_runtime.h>

// MotorLayer: out[j] = sum_i weight[j,i] * input[i, j<3 ? 0 : 1]
// input: [8388608, 2] fp32 interleaved; weight: [6, 8388608] fp32; out: [6] fp32.
// Pure HBM-streaming reduction (~268 MB). Two-kernel deterministic reduce.

#define N_IN      8388608
#define N4        (N_IN / 4)          // float4 chunks per weight row
#define BLOCKS_R1 2048
#define THREADS_R1 256
#define THREADS_R2 256

// Per-block partials scratch (no dynamic allocation allowed).
__device__ float g_partials[BLOCKS_R1 * 6];

__global__ __launch_bounds__(THREADS_R1)
void motor_reduce1(const float4* __restrict__ inpv,   // N4*2 float4 (pairs interleaved)
                   const float4* __restrict__ wv)     // 6 rows x N4 float4
{
    float s0 = 0.f, s1 = 0.f, s2 = 0.f, s3 = 0.f, s4 = 0.f, s5 = 0.f;

    const int stride = gridDim.x * blockDim.x;
    for (int it = blockIdx.x * blockDim.x + threadIdx.x; it < N4; it += stride) {
        // input pairs: p = (x_i, y_i, x_{i+1}, y_{i+1}); q = (x_{i+2}, y_{i+2}, x_{i+3}, y_{i+3})
        float4 p = inpv[it * 2 + 0];
        float4 q = inpv[it * 2 + 1];

        float4 w0 = wv[0 * N4 + it];
        float4 w1 = wv[1 * N4 + it];
        float4 w2 = wv[2 * N4 + it];
        float4 w3 = wv[3 * N4 + it];
        float4 w4 = wv[4 * N4 + it];
        float4 w5 = wv[5 * N4 + it];

        // rows 0..2 contract with x-components, rows 3..5 with y-components
        s0 += w0.x * p.x + w0.y * p.z + w0.z * q.x + w0.w * q.z;
        s1 += w1.x * p.x + w1.y * p.z + w1.z * q.x + w1.w * q.z;
        s2 += w2.x * p.x + w2.y * p.z + w2.z * q.x + w2.w * q.z;
        s3 += w3.x * p.y + w3.y * p.w + w3.z * q.y + w3.w * q.w;
        s4 += w4.x * p.y + w4.y * p.w + w4.z * q.y + w4.w * q.w;
        s5 += w5.x * p.y + w5.y * p.w + w5.z * q.y + w5.w * q.w;
    }

    // Warp reduction (deterministic fixed pattern)
    #pragma unroll
    for (int off = 16; off > 0; off >>= 1) {
        s0 += __shfl_down_sync(0xffffffffu, s0, off);
        s1 += __shfl_down_sync(0xffffffffu, s1, off);
        s2 += __shfl_down_sync(0xffffffffu, s2, off);
        s3 += __shfl_down_sync(0xffffffffu, s3, off);
        s4 += __shfl_down_sync(0xffffffffu, s4, off);
        s5 += __shfl_down_sync(0xffffffffu, s5, off);
    }

    __shared__ float smem[THREADS_R1 / 32][6];
    const int warp = threadIdx.x >> 5;
    const int lane = threadIdx.x & 31;
    if (lane == 0) {
        smem[warp][0] = s0; smem[warp][1] = s1; smem[warp][2] = s2;
        smem[warp][3] = s3; smem[warp][4] = s4; smem[warp][5] = s5;
    }
    __syncthreads();

    if (threadIdx.x == 0) {
        float t0 = 0.f, t1 = 0.f, t2 = 0.f, t3 = 0.f, t4 = 0.f, t5 = 0.f;
        #pragma unroll
        for (int w = 0; w < THREADS_R1 / 32; w++) {
            t0 += smem[w][0]; t1 += smem[w][1]; t2 += smem[w][2];
            t3 += smem[w][3]; t4 += smem[w][4]; t5 += smem[w][5];
        }
        float* dst = &g_partials[blockIdx.x * 6];
        dst[0] = t0; dst[1] = t1; dst[2] = t2;
        dst[3] = t3; dst[4] = t4; dst[5] = t5;
    }
}

__global__ __launch_bounds__(THREADS_R2)
void motor_reduce2(float* __restrict__ out)
{
    // blockIdx.x = output index j in [0,6). Fixed-order tree reduce of BLOCKS_R1 partials.
    const int j = blockIdx.x;
    float s = 0.f;
    for (int b = threadIdx.x; b < BLOCKS_R1; b += THREADS_R2)
        s += g_partials[b * 6 + j];

    #pragma unroll
    for (int off = 16; off > 0; off >>= 1)
        s += __shfl_down_sync(0xffffffffu, s, off);

    __shared__ float smem[THREADS_R2 / 32];
    const int warp = threadIdx.x >> 5;
    const int lane = threadIdx.x & 31;
    if (lane == 0) smem[warp] = s;
    __syncthreads();

    if (threadIdx.x == 0) {
        float t = 0.f;
        #pragma unroll
        for (int w = 0; w < THREADS_R2 / 32; w++) t += smem[w];
        out[j] = t;
    }
}

extern "C" void kernel_launch(void* const* d_in, const int* in_sizes, int n_in,
                              void* d_out, int out_size) {
    const float4* inpv = (const float4*)d_in[0];   // input  [8388608, 2] fp32
    const float4* wv   = (const float4*)d_in[1];   // weight [6, 8388608] fp32
    float* out = (float*)d_out;

    motor_reduce1<<<BLOCKS_R1, THREADS_R1>>>(inpv, wv);
    motor_reduce2<<<6, THREADS_R2>>>(out);
}

// round 2
// speedup vs baseline: 1.0349x; 1.0349x over previous
#include <cuda_runtime.h>

// MotorLayer: out[j] = sum_i weight[j,i] * input[i, j<3 ? 0 : 1]
// input: [8388608, 2] fp32 interleaved; weight: [6, 8388608] fp32; out: [6] fp32.
// Single fused kernel: grid-stride streaming reduce + threadfence last-block finish.
// ~268 MB HBM traffic, read-once -> __ldcs streaming loads.

#define N_IN      8388608
#define N4        (N_IN / 4)          // float4 chunks per weight row
#define BLOCKS    2048
#define THREADS   256

__device__ float g_partials[BLOCKS * 6];
__device__ unsigned int g_count = 0;   // reset to 0 by last block each call

__global__ __launch_bounds__(THREADS)
void motor_fused(const float4* __restrict__ inpv,   // N4*2 float4 (pairs interleaved)
                 const float4* __restrict__ wv,     // 6 rows x N4 float4
                 float* __restrict__ out)
{
    float s0 = 0.f, s1 = 0.f, s2 = 0.f, s3 = 0.f, s4 = 0.f, s5 = 0.f;

    const int stride = gridDim.x * blockDim.x;
    for (int it = blockIdx.x * blockDim.x + threadIdx.x; it < N4; it += stride) {
        float4 p  = __ldcs(&inpv[it * 2 + 0]);
        float4 q  = __ldcs(&inpv[it * 2 + 1]);
        float4 w0 = __ldcs(&wv[0 * N4 + it]);
        float4 w1 = __ldcs(&wv[1 * N4 + it]);
        float4 w2 = __ldcs(&wv[2 * N4 + it]);
        float4 w3 = __ldcs(&wv[3 * N4 + it]);
        float4 w4 = __ldcs(&wv[4 * N4 + it]);
        float4 w5 = __ldcs(&wv[5 * N4 + it]);

        s0 += w0.x * p.x + w0.y * p.z + w0.z * q.x + w0.w * q.z;
        s1 += w1.x * p.x + w1.y * p.z + w1.z * q.x + w1.w * q.z;
        s2 += w2.x * p.x + w2.y * p.z + w2.z * q.x + w2.w * q.z;
        s3 += w3.x * p.y + w3.y * p.w + w3.z * q.y + w3.w * q.w;
        s4 += w4.x * p.y + w4.y * p.w + w4.z * q.y + w4.w * q.w;
        s5 += w5.x * p.y + w5.y * p.w + w5.z * q.y + w5.w * q.w;
    }

    // Warp reduction (fixed pattern, deterministic)
    #pragma unroll
    for (int off = 16; off > 0; off >>= 1) {
        s0 += __shfl_down_sync(0xffffffffu, s0, off);
        s1 += __shfl_down_sync(0xffffffffu, s1, off);
        s2 += __shfl_down_sync(0xffffffffu, s2, off);
        s3 += __shfl_down_sync(0xffffffffu, s3, off);
        s4 += __shfl_down_sync(0xffffffffu, s4, off);
        s5 += __shfl_down_sync(0xffffffffu, s5, off);
    }

    __shared__ float smem[THREADS / 32][6];
    const int warp = threadIdx.x >> 5;
    const int lane = threadIdx.x & 31;
    if (lane == 0) {
        smem[warp][0] = s0; smem[warp][1] = s1; smem[warp][2] = s2;
        smem[warp][3] = s3; smem[warp][4] = s4; smem[warp][5] = s5;
    }
    __syncthreads();

    __shared__ bool is_last;
    if (threadIdx.x == 0) {
        float t0 = 0.f, t1 = 0.f, t2 = 0.f, t3 = 0.f, t4 = 0.f, t5 = 0.f;
        #pragma unroll
        for (int w = 0; w < THREADS / 32; w++) {
            t0 += smem[w][0]; t1 += smem[w][1]; t2 += smem[w][2];
            t3 += smem[w][3]; t4 += smem[w][4]; t5 += smem[w][5];
        }
        float* dst = &g_partials[blockIdx.x * 6];
        dst[0] = t0; dst[1] = t1; dst[2] = t2;
        dst[3] = t3; dst[4] = t4; dst[5] = t5;
        // Make partials visible device-wide before signaling completion.
        __threadfence();
        unsigned int prev = atomicAdd(&g_count, 1u);
        is_last = (prev == (unsigned int)(gridDim.x - 1));
    }
    __syncthreads();

    if (!is_last) return;

    // Last block: reduce BLOCKS x 6 partials (L2-resident, ~49 KB).
    {
        float t0 = 0.f, t1 = 0.f, t2 = 0.f, t3 = 0.f, t4 = 0.f, t5 = 0.f;
        for (int b = threadIdx.x; b < BLOCKS; b += THREADS) {
            const float* src = &g_partials[b * 6];
            t0 += src[0]; t1 += src[1]; t2 += src[2];
            t3 += src[3]; t4 += src[4]; t5 += src[5];
        }
        #pragma unroll
        for (int off = 16; off > 0; off >>= 1) {
            t0 += __shfl_down_sync(0xffffffffu, t0, off);
            t1 += __shfl_down_sync(0xffffffffu, t1, off);
            t2 += __shfl_down_sync(0xffffffffu, t2, off);
            t3 += __shfl_down_sync(0xffffffffu, t3, off);
            t4 += __shfl_down_sync(0xffffffffu, t4, off);
            t5 += __shfl_down_sync(0xffffffffu, t5, off);
        }
        __syncthreads();   // smem reuse barrier
        if (lane == 0) {
            smem[warp][0] = t0; smem[warp][1] = t1; smem[warp][2] = t2;
            smem[warp][3] = t3; smem[warp][4] = t4; smem[warp][5] = t5;
        }
        __syncthreads();
        if (threadIdx.x == 0) {
            float r0 = 0.f, r1 = 0.f, r2 = 0.f, r3 = 0.f, r4 = 0.f, r5 = 0.f;
            #pragma unroll
            for (int w = 0; w < THREADS / 32; w++) {
                r0 += smem[w][0]; r1 += smem[w][1]; r2 += smem[w][2];
                r3 += smem[w][3]; r4 += smem[w][4]; r5 += smem[w][5];
            }
            out[0] = r0; out[1] = r1; out[2] = r2;
            out[3] = r3; out[4] = r4; out[5] = r5;
            g_count = 0;   // reset for next (graph-replayed) call
        }
    }
}

extern "C" void kernel_launch(void* const* d_in, const int* in_sizes, int n_in,
                              void* d_out, int out_size) {
    const float4* inpv = (const float4*)d_in[0];   // input  [8388608, 2] fp32
    const float4* wv   = (const float4*)d_in[1];   // weight [6, 8388608] fp32
    float* out = (float*)d_out;

    motor_fused<<<BLOCKS, THREADS>>>(inpv, wv, out);
}